// round 9
// baseline (speedup 1.0000x reference)
#include <cuda_runtime.h>
#include <cuda_fp16.h>
#include <cstdint>

#define DEV_INLINE __device__ __forceinline__

// ---------------- problem sizes ----------------
static constexpr int kB = 16384;
static constexpr int kD = 1024;
static constexpr int kU = 128;

// ---------------- spline kernel tiling ----------------
static constexpr int S_DC  = 32;                 // K per chunk
static constexpr int S_NCH = kD / S_DC;          // 32
static constexpr int PAIR_BYTES = 128 * 128;     // 16384 (128 rows x 128B)
static constexpr int S_AREG = 3 * PAIR_BYTES;    // 49152 A region (3 pairs)
static constexpr int S_BUF  = 2 * S_AREG;        // 98304 (A + W regions)
static constexpr int S_SMEM = 2 * S_BUF;         // 196608 double buffered
static constexpr int S_W_U4 = 3 * PAIR_BYTES / 16;  // 3072 uint4 per chunk

// ---------------- base kernel tiling ----------------
static constexpr int B_DC  = 64;                 // K per chunk
static constexpr int B_NCH = kD / B_DC;          // 16
static constexpr int B_AREG = PAIR_BYTES;        // 16384
static constexpr int B_BUF  = 2 * B_AREG;        // 32768
static constexpr int B_SMEM = 2 * B_BUF;         // 65536
static constexpr int B_W_U4 = PAIR_BYTES / 16;   // 1024 uint4 per chunk

// packed weights
__device__ __half g_WbPack[16 * 8192];           // base:   [c16][n128][k64] SW128
__device__ __half g_WsPack[96 * 8192];           // spline: [c32][p3][n128][64h] SW128

// ---------------- PTX helpers ----------------
DEV_INLINE uint32_t smem_u32(const void* p) {
    uint32_t a;
    asm("{ .reg .u64 t; cvta.to.shared.u64 t, %1; cvt.u32.u64 %0, t; }" : "=r"(a) : "l"(p));
    return a;
}

#define LDSM_X4(r, addr)                                                        \
    asm volatile("ldmatrix.sync.aligned.m8n8.x4.shared.b16 {%0,%1,%2,%3}, [%4];"\
                 : "=r"((r)[0]), "=r"((r)[1]), "=r"((r)[2]), "=r"((r)[3])       \
                 : "r"(addr))

DEV_INLINE void mma16816(float* d, const uint32_t* a, uint32_t b0, uint32_t b1) {
    asm volatile(
        "mma.sync.aligned.m16n8k16.row.col.f32.f16.f16.f32 "
        "{%0,%1,%2,%3}, {%4,%5,%6,%7}, {%8,%9}, {%0,%1,%2,%3};"
        : "+f"(d[0]), "+f"(d[1]), "+f"(d[2]), "+f"(d[3])
        : "r"(a[0]), "r"(a[1]), "r"(a[2]), "r"(a[3]), "r"(b0), "r"(b1));
}

DEV_INLINE void cp_async16(uint32_t smem_dst, const void* gsrc) {
    asm volatile("cp.async.cg.shared.global [%0], [%1], 16;"
                 :: "r"(smem_dst), "l"(gsrc) : "memory");
}
DEV_INLINE void cp_async_commit() { asm volatile("cp.async.commit_group;" ::: "memory"); }
DEV_INLINE void cp_async_wait_all() { asm volatile("cp.async.wait_group 0;" ::: "memory"); }

// ---------------- weight prep ----------------
__global__ void kan_prep_weights(const float* __restrict__ bw,
                                 const float* __restrict__ sw) {
    int idx = blockIdx.x * blockDim.x + threadIdx.x;
    if (idx < 131072) {
        // base pack: [c16][n128][k64 halves]
        int k = idx & 63, n = (idx >> 6) & 127, c = idx >> 13;
        int i = c * 64 + k;
        unsigned off = (unsigned)(n * 128 + k * 2);
        unsigned swz = off ^ ((off >> 3) & 0x70);
        g_WbPack[(size_t)c * 8192 + (swz >> 1)] = __float2half(bw[i * kU + n]);
    } else {
        // spline pack: [c32][p3][n128][hw64], streams g = p*2 + (hw>>5), g<5
        int j  = idx - 131072;
        int hw = j & 63, n = (j >> 6) & 127, t3 = j >> 13;  // t3 = c*3+p
        int p  = t3 % 3, c = t3 / 3;
        int slo = hw >> 5, k = hw & 31;
        int g = p * 2 + slo;
        int i = c * 32 + k;
        unsigned off = (unsigned)(n * 128 + slo * 64 + k * 2);
        unsigned swz = off ^ ((off >> 3) & 0x70);
        float v = (g < 5) ? sw[(size_t)(i * kU + n) * 8 + g] : 0.f;
        g_WsPack[(size_t)t3 * 8192 + (swz >> 1)] = __float2half(v);
    }
}

// ---- consumer load/mma macros (64x64 warp tile) ----
// FB layout: [bh*8 + h*4 + nbi]
#define LD_FRAGS(AOFF, BOFF, J, FA, FB) do {                                    \
    LDSM_X4(&(FB)[0],  bAddr[0][J] + (BOFF));                                   \
    LDSM_X4(&(FB)[4],  (bAddr[0][J] + (BOFF)) ^ 16u);                           \
    LDSM_X4(&(FB)[8],  bAddr[1][J] + (BOFF));                                   \
    LDSM_X4(&(FB)[12], (bAddr[1][J] + (BOFF)) ^ 16u);                           \
    LDSM_X4(&(FA)[0],  aAddr[0][J] + (AOFF));                                   \
    LDSM_X4(&(FA)[4],  aAddr[1][J] + (AOFF));                                   \
    LDSM_X4(&(FA)[8],  aAddr[2][J] + (AOFF));                                   \
    LDSM_X4(&(FA)[12], aAddr[3][J] + (AOFF));                                   \
} while (0)

#define MMA_FRAGS(FA, FB) do {                                                  \
    _Pragma("unroll")                                                           \
    for (int mb_ = 0; mb_ < 4; ++mb_)                                           \
        _Pragma("unroll")                                                       \
        for (int bh_ = 0; bh_ < 2; ++bh_)                                       \
            _Pragma("unroll")                                                   \
            for (int nbi_ = 0; nbi_ < 4; ++nbi_)                                \
                mma16816(acc[mb_][bh_ * 4 + nbi_], &(FA)[mb_ * 4],              \
                         (FB)[bh_ * 8 + nbi_], (FB)[bh_ * 8 + 4 + nbi_]);       \
} while (0)

// =======================================================================
// BASE kernel: out = SiLU(x @ Wb)
// =======================================================================
__global__ void __launch_bounds__(256, 1)
kan_base_kernel(const float* __restrict__ x, float* __restrict__ out) {
    extern __shared__ char smem[];
    const uint32_t smem_base = smem_u32(smem);
    const int tid  = threadIdx.x;
    const int wid  = tid >> 5;
    const int lane = tid & 31;
    const int row_base = blockIdx.x * 128;

    if (wid < 4) {
        // ---- producers: 128 threads, 1 row each, convert x -> fp16 SW128 ----
        const int pr = tid;
        const float* xp = x + (size_t)(row_base + pr) * kD;
        const unsigned rowOff = (unsigned)(pr * 128);
        const unsigned rXor   = (unsigned)((pr & 7) << 4);

        float4 xq[16];
        auto loadX = [&](int c) {
            const float* p = xp + c * B_DC;
            #pragma unroll
            for (int j = 0; j < 16; ++j)
                xq[j] = *reinterpret_cast<const float4*>(p + j * 4);
        };
        auto produce = [&](uint32_t bufOff) {
            #pragma unroll
            for (int g = 0; g < 8; ++g) {
                union { __half2 h2[4]; uint4 u4; } st;
                st.h2[0] = __floats2half2_rn(xq[2*g].x,   xq[2*g].y);
                st.h2[1] = __floats2half2_rn(xq[2*g].z,   xq[2*g].w);
                st.h2[2] = __floats2half2_rn(xq[2*g+1].x, xq[2*g+1].y);
                st.h2[3] = __floats2half2_rn(xq[2*g+1].z, xq[2*g+1].w);
                unsigned off = rowOff + g * 16;
                unsigned swz = off ^ rXor;
                *reinterpret_cast<uint4*>(smem + bufOff + swz) = st.u4;
            }
        };
        auto copyW = [&](int c, uint32_t bufOff) {
            const char* src = reinterpret_cast<const char*>(g_WbPack) + (size_t)c * 16384;
            #pragma unroll
            for (int j = 0; j < B_W_U4 / 128; ++j) {  // 8 per thread
                int i = pr + j * 128;
                cp_async16(smem_base + bufOff + B_AREG + i * 16, src + i * 16);
            }
            cp_async_commit();
        };

        // prologue
        copyW(0, 0);
        loadX(0);
        produce(0);
        loadX(1);
        cp_async_wait_all();
        __syncthreads();

        for (int c = 0; c < B_NCH; ++c) {
            if (c + 1 < B_NCH) {
                uint32_t bo = (uint32_t)(((c + 1) & 1) * B_BUF);
                copyW(c + 1, bo);
                produce(bo);
                if (c + 2 < B_NCH) loadX(c + 2);
                cp_async_wait_all();
            }
            __syncthreads();
        }
    } else {
        // ---- consumers: 4 warps, 64x64 tiles ----
        const int w  = wid - 4;
        const int mi = w & 1;
        const int ni = w >> 1;

        float acc[4][8][4];
        #pragma unroll
        for (int a = 0; a < 4; ++a)
            #pragma unroll
            for (int b = 0; b < 8; ++b)
                #pragma unroll
                for (int j = 0; j < 4; ++j) acc[a][b][j] = 0.f;

        const int aRowLocal  = (lane & 7) + ((lane >> 3) & 1) * 8;
        const uint32_t kbAhi = ((lane >> 4) & 1) * 16;

        uint32_t aAddr[4][4], bAddr[2][4];
        #pragma unroll
        for (int mb = 0; mb < 4; ++mb) {
            int r = mi * 64 + mb * 16 + aRowLocal;
            uint32_t base = smem_base + (uint32_t)(r * 128);
            uint32_t ax   = (uint32_t)((r & 7) << 4);
            #pragma unroll
            for (int j = 0; j < 4; ++j)
                aAddr[mb][j] = base + (((uint32_t)(j * 32) + kbAhi) ^ ax);
        }
        #pragma unroll
        for (int bh = 0; bh < 2; ++bh) {
            int rn = ni * 64 + bh * 32 + lane;
            uint32_t base = smem_base + (uint32_t)B_AREG + (uint32_t)(rn * 128);
            uint32_t bx   = (uint32_t)((rn & 7) << 4);
            #pragma unroll
            for (int j = 0; j < 4; ++j)
                bAddr[bh][j] = base + (((uint32_t)(j * 32)) ^ bx);
        }

        __syncthreads();

        uint32_t fa0[16], fa1[16], fb0[16], fb1[16];
        for (int c = 0; c < B_NCH; ++c) {
            const uint32_t bo = (uint32_t)((c & 1) * B_BUF);
            LD_FRAGS(bo, bo, 0, fa0, fb0);
            LD_FRAGS(bo, bo, 1, fa1, fb1);  MMA_FRAGS(fa0, fb0);
            LD_FRAGS(bo, bo, 2, fa0, fb0);  MMA_FRAGS(fa1, fb1);
            LD_FRAGS(bo, bo, 3, fa1, fb1);  MMA_FRAGS(fa0, fb0);
                                            MMA_FRAGS(fa1, fb1);
            __syncthreads();
        }

        // epilogue: SiLU, store
        const int colBase = ni * 64 + (lane & 3) * 2;
        #pragma unroll
        for (int mb = 0; mb < 4; ++mb) {
            int row0 = row_base + mi * 64 + mb * 16 + (lane >> 2);
            #pragma unroll
            for (int nb = 0; nb < 8; ++nb) {
                int col = colBase + (nb >> 2) * 32 + (nb & 3) * 8;
                float z0 = acc[mb][nb][0], z1 = acc[mb][nb][1];
                float z2 = acc[mb][nb][2], z3 = acc[mb][nb][3];
                float2 v0, v1;
                v0.x = __fdividef(z0, 1.f + __expf(-z0));
                v0.y = __fdividef(z1, 1.f + __expf(-z1));
                v1.x = __fdividef(z2, 1.f + __expf(-z2));
                v1.y = __fdividef(z3, 1.f + __expf(-z3));
                *reinterpret_cast<float2*>(out + (size_t)row0 * kU + col)       = v0;
                *reinterpret_cast<float2*>(out + (size_t)(row0 + 8) * kU + col) = v1;
            }
        }
    }
}

// =======================================================================
// SPLINE kernel: out += einsum(rbf(x), Ws)   (out already holds SiLU(base))
// =======================================================================
__global__ void __launch_bounds__(256, 1)
kan_spline_kernel(const float* __restrict__ x, float* __restrict__ out) {
    extern __shared__ char smem[];
    const uint32_t smem_base = smem_u32(smem);
    const int tid  = threadIdx.x;
    const int wid  = tid >> 5;
    const int lane = tid & 31;
    const int row_base = blockIdx.x * 128;

    const float E375p = 42.52108200006278f;    // e^{3.75}
    const float E125p = 3.4903429574597902f;   // e^{1.25}
    const float E125m = 0.2865047968601901f;   // e^{-1.25}
    const float E375m = 0.023517745856009107f; // e^{-3.75}

    if (wid < 4) {
        // ---- producers: 128 threads, 1 row each, rbf streams ----
        const int pr = tid;
        const float* xp = x + (size_t)(row_base + pr) * kD;
        const unsigned rowOff = (unsigned)(pr * 128);
        const unsigned rXor   = (unsigned)((pr & 7) << 4);

        float4 xq[8];
        auto loadX = [&](int c) {
            const float* p = xp + c * S_DC;
            #pragma unroll
            for (int j = 0; j < 8; ++j)
                xq[j] = *reinterpret_cast<const float4*>(p + j * 4);
        };
        auto produce = [&](uint32_t bufOff) {
            #pragma unroll
            for (int g = 0; g < 4; ++g) {
                float xs[8];
                xs[0]=xq[2*g].x;   xs[1]=xq[2*g].y;   xs[2]=xq[2*g].z;   xs[3]=xq[2*g].w;
                xs[4]=xq[2*g+1].x; xs[5]=xq[2*g+1].y; xs[6]=xq[2*g+1].z; xs[7]=xq[2*g+1].w;
                union { __half2 h2[4]; uint4 u4; } st[5];
                #pragma unroll
                for (int e = 0; e < 8; e += 2) {
                    float a0 = xs[e] + 1.f, a1 = xs[e+1] + 1.f;
                    float y0a = __expf(-5.f * a0 * a0);
                    float y0b = __expf(-5.f * a1 * a1);
                    float ta  = __expf(5.f * xs[e]);
                    float tb  = __expf(5.f * xs[e+1]);
                    float y1a = y0a * ta * E375p, y1b = y0b * tb * E375p;
                    float y2a = y1a * ta * E125p, y2b = y1b * tb * E125p;
                    float y3a = y2a * ta * E125m, y3b = y2b * tb * E125m;
                    float y4a = y3a * ta * E375m, y4b = y3b * tb * E375m;
                    int j = e >> 1;
                    st[0].h2[j] = __floats2half2_rn(y0a, y0b);
                    st[1].h2[j] = __floats2half2_rn(y1a, y1b);
                    st[2].h2[j] = __floats2half2_rn(y2a, y2b);
                    st[3].h2[j] = __floats2half2_rn(y3a, y3b);
                    st[4].h2[j] = __floats2half2_rn(y4a, y4b);
                }
                #pragma unroll
                for (int s = 0; s < 5; ++s) {
                    int p = s >> 1, slo = s & 1;
                    unsigned off = rowOff + (unsigned)(slo * 64 + g * 16);
                    unsigned swz = off ^ rXor;
                    *reinterpret_cast<uint4*>(smem + bufOff + p * PAIR_BYTES + swz)
                        = st[s].u4;
                }
            }
        };
        auto copyW = [&](int c, uint32_t bufOff) {
            const char* src = reinterpret_cast<const char*>(g_WsPack) +
                              (size_t)c * (3 * 16384);
            #pragma unroll
            for (int j = 0; j < S_W_U4 / 128; ++j) {  // 24 per thread
                int i = pr + j * 128;
                cp_async16(smem_base + bufOff + S_AREG + i * 16, src + i * 16);
            }
            cp_async_commit();
        };

        // prologue
        copyW(0, 0);
        loadX(0);
        produce(0);
        loadX(1);
        cp_async_wait_all();
        __syncthreads();

        for (int c = 0; c < S_NCH; ++c) {
            if (c + 1 < S_NCH) {
                uint32_t bo = (uint32_t)(((c + 1) & 1) * S_BUF);
                copyW(c + 1, bo);
                produce(bo);
                if (c + 2 < S_NCH) loadX(c + 2);
                cp_async_wait_all();
            }
            __syncthreads();
        }
    } else {
        // ---- consumers: 4 warps, 64x64 tiles, 10 steps/chunk ----
        const int w  = wid - 4;
        const int mi = w & 1;
        const int ni = w >> 1;

        float acc[4][8][4];
        #pragma unroll
        for (int a = 0; a < 4; ++a)
            #pragma unroll
            for (int b = 0; b < 8; ++b)
                #pragma unroll
                for (int j = 0; j < 4; ++j) acc[a][b][j] = 0.f;

        const int aRowLocal  = (lane & 7) + ((lane >> 3) & 1) * 8;
        const uint32_t kbAhi = ((lane >> 4) & 1) * 16;

        uint32_t aAddr[4][4], bAddr[2][4];
        #pragma unroll
        for (int mb = 0; mb < 4; ++mb) {
            int r = mi * 64 + mb * 16 + aRowLocal;
            uint32_t base = smem_base + (uint32_t)(r * 128);
            uint32_t ax   = (uint32_t)((r & 7) << 4);
            #pragma unroll
            for (int j = 0; j < 4; ++j)
                aAddr[mb][j] = base + (((uint32_t)(j * 32) + kbAhi) ^ ax);
        }
        #pragma unroll
        for (int bh = 0; bh < 2; ++bh) {
            int rn = ni * 64 + bh * 32 + lane;
            uint32_t base = smem_base + (uint32_t)S_AREG + (uint32_t)(rn * 128);
            uint32_t bx   = (uint32_t)((rn & 7) << 4);
            #pragma unroll
            for (int j = 0; j < 4; ++j)
                bAddr[bh][j] = base + (((uint32_t)(j * 32)) ^ bx);
        }

        __syncthreads();

        // step T (0..9): s = T/2, kk = T&1; pair p = s>>1; j = (s&1)*2 + kk
#define S_LD(T, FA, FB) do {                                                    \
        constexpr int s_ = (T) / 2, kk_ = (T) & 1;                              \
        constexpr uint32_t pOff_ = (uint32_t)((s_ >> 1) * PAIR_BYTES);          \
        constexpr int j_ = (s_ & 1) * 2 + kk_;                                  \
        LD_FRAGS(bo + pOff_, bo + pOff_, j_, FA, FB);                           \
} while (0)

        uint32_t fa0[16], fa1[16], fb0[16], fb1[16];
        for (int c = 0; c < S_NCH; ++c) {
            const uint32_t bo = (uint32_t)((c & 1) * S_BUF);
            S_LD(0, fa0, fb0);
            S_LD(1, fa1, fb1);  MMA_FRAGS(fa0, fb0);
            S_LD(2, fa0, fb0);  MMA_FRAGS(fa1, fb1);
            S_LD(3, fa1, fb1);  MMA_FRAGS(fa0, fb0);
            S_LD(4, fa0, fb0);  MMA_FRAGS(fa1, fb1);
            S_LD(5, fa1, fb1);  MMA_FRAGS(fa0, fb0);
            S_LD(6, fa0, fb0);  MMA_FRAGS(fa1, fb1);
            S_LD(7, fa1, fb1);  MMA_FRAGS(fa0, fb0);
            S_LD(8, fa0, fb0);  MMA_FRAGS(fa1, fb1);
            S_LD(9, fa1, fb1);  MMA_FRAGS(fa0, fb0);
                                MMA_FRAGS(fa1, fb1);
            __syncthreads();
        }
#undef S_LD

        // epilogue: out += spline
        const int colBase = ni * 64 + (lane & 3) * 2;
        #pragma unroll
        for (int mb = 0; mb < 4; ++mb) {
            int row0 = row_base + mi * 64 + mb * 16 + (lane >> 2);
            #pragma unroll
            for (int nb = 0; nb < 8; ++nb) {
                int col = colBase + (nb >> 2) * 32 + (nb & 3) * 8;
                float2* p0 = reinterpret_cast<float2*>(out + (size_t)row0 * kU + col);
                float2* p1 = reinterpret_cast<float2*>(out + (size_t)(row0 + 8) * kU + col);
                float2 v0 = *p0, v1 = *p1;
                v0.x += acc[mb][nb][0]; v0.y += acc[mb][nb][1];
                v1.x += acc[mb][nb][2]; v1.y += acc[mb][nb][3];
                *p0 = v0; *p1 = v1;
            }
        }
    }
}

// ---------------- launch ----------------
extern "C" void kernel_launch(void* const* d_in, const int* in_sizes, int n_in,
                              void* d_out, int out_size) {
    (void)in_sizes; (void)n_in; (void)out_size;
    const float* x  = (const float*)d_in[0];
    const float* bw = (const float*)d_in[1];
    const float* sw = (const float*)d_in[2];
    float* out = (float*)d_out;

    cudaFuncSetAttribute(kan_base_kernel,
                         cudaFuncAttributeMaxDynamicSharedMemorySize, B_SMEM);
    cudaFuncSetAttribute(kan_spline_kernel,
                         cudaFuncAttributeMaxDynamicSharedMemorySize, S_SMEM);

    kan_prep_weights<<<(131072 + 786432) / 256, 256>>>(bw, sw);
    kan_base_kernel<<<kB / 128, 256, B_SMEM>>>(x, out);
    kan_spline_kernel<<<kB / 128, 256, S_SMEM>>>(x, out);
}